// round 4
// baseline (speedup 1.0000x reference)
#include <cuda_runtime.h>
#include <cstdint>

#define NE 100000
#define NA 10000

// Scratch (static device globals — no allocation)
static __device__ float g_uncf[NA * 40 * 32];   // uncoupled features per atom
static __device__ float g_pool[NA * 40 * 32];   // pooled messages per atom

__device__ __forceinline__ int dd2g(int dd) { return (dd == 0) ? 0 : (dd < 4) ? 1 : (dd < 13) ? 2 : 3; }
__device__ __forceinline__ int goff_u(int g) { return (g == 0) ? 0 : (g == 1) ? 1 : (g == 2) ? 13 : 94; }
__device__ __forceinline__ int goff_d(int g) { return (g == 0) ? 0 : (g == 1) ? 1 : (g == 2) ? 4 : 13; }
__device__ __forceinline__ int pow3g(int g)  { return (g == 0) ? 1 : (g == 1) ? 3 : (g == 2) ? 9 : 27; }

// ---------------------------------------------------------------------------
// compile-time-specialized uncoupled dot
// ---------------------------------------------------------------------------
template <int G>
__device__ __forceinline__ float uncf_dot(const float* __restrict__ Us,
                                          const float* __restrict__ fs,
                                          int ub, int lane)
{
    const int chb = 32 * (3 - G) + lane;
    float acc = Us[ub] * fs[chb];
    if (G >= 1) {
        #pragma unroll
        for (int mm = 0; mm < 3; mm++) acc = fmaf(Us[ub + 1 + mm], fs[128 + chb + mm * 96], acc);
    }
    if (G >= 2) {
        #pragma unroll
        for (int mm = 0; mm < 5; mm++) acc = fmaf(Us[ub + 4 + mm], fs[416 + chb + mm * 64], acc);
    }
    if (G >= 3) {
        #pragma unroll
        for (int mm = 0; mm < 7; mm++) acc = fmaf(Us[ub + 9 + mm], fs[736 + chb + mm * 32], acc);
    }
    return acc;
}

// ---------------------------------------------------------------------------
// K1: per-atom uncoupled features  g_uncf[n][dd][k]
// ---------------------------------------------------------------------------
__global__ void __launch_bounds__(256) k_uncf(
    const float* __restrict__ f0, const float* __restrict__ f1,
    const float* __restrict__ f2, const float* __restrict__ f3,
    const float* __restrict__ U0, const float* __restrict__ U1,
    const float* __restrict__ U2, const float* __restrict__ U3)
{
    __shared__ float fs[960];
    __shared__ float Us[526];
    const int n = blockIdx.x, t = threadIdx.x;
    if (t < 240) {
        float4 v;
        if      (t < 32)  v = ((const float4*)f0)[(size_t)n * 32 + t];
        else if (t < 104) v = ((const float4*)f1)[(size_t)n * 72 + (t - 32)];
        else if (t < 184) v = ((const float4*)f2)[(size_t)n * 80 + (t - 104)];
        else              v = ((const float4*)f3)[(size_t)n * 56 + (t - 184)];
        ((float4*)fs)[t] = v;
    }
    if (t == 0) Us[0] = U0[0];
    for (int i = t; i < 12;  i += 256) Us[1  + i] = U1[i];
    for (int i = t; i < 81;  i += 256) Us[13 + i] = U2[i];
    for (int i = t; i < 432; i += 256) Us[94 + i] = U3[i];
    __syncthreads();

    const int lane = t & 31, row = t >> 5;
    float* outp = g_uncf + (size_t)n * 1280;
    #pragma unroll
    for (int i = 0; i < 5; i++) {
        int dd = row + 8 * i;
        int g  = dd2g(dd);
        int d  = dd - goff_d(g);
        int ub = goff_u(g) + d * (g + 1) * (g + 1);
        float v;
        switch (g) {
            case 0:  v = uncf_dot<0>(Us, fs, ub, lane); break;
            case 1:  v = uncf_dot<1>(Us, fs, ub, lane); break;
            case 2:  v = uncf_dot<2>(Us, fs, ub, lane); break;
            default: v = uncf_dot<3>(Us, fs, ub, lane); break;
        }
        outp[dd * 32 + lane] = v;
    }
}

// ---------------------------------------------------------------------------
// K2: warp = 4 edges x 8 k-quads. float4 gather (LDG.128) + red.global.add.v4.f32
// ---------------------------------------------------------------------------
__global__ void __launch_bounds__(256) k_edge(
    const float* __restrict__ rr,
    const float* __restrict__ sh0, const float* __restrict__ sh1,
    const float* __restrict__ sh2, const float* __restrict__ sh3,
    const float* __restrict__ W0, const float* __restrict__ W1,
    const float* __restrict__ W2, const float* __restrict__ W3,
    const float* __restrict__ U0, const float* __restrict__ U1,
    const float* __restrict__ U2, const float* __restrict__ U3,
    const int* __restrict__ centers, const int* __restrict__ neighbors)
{
    __shared__ float4 Ws4[640];          // Wrad0..3 concat in float4: offsets 0,256,448,576
    __shared__ float  Us[526];           // U0..3 concat
    __shared__ float4 seS[8][4][40];     // per-warp, per-edge S table [dd][lp in xyzw]
    __shared__ float  shS[8][4][16];     // per-warp, per-edge sh values

    const int t = threadIdx.x;
    for (int i = t; i < 640; i += 256) {
        float4 v;
        if      (i < 256) v = ((const float4*)W0)[i];
        else if (i < 448) v = ((const float4*)W1)[i - 256];
        else if (i < 576) v = ((const float4*)W2)[i - 448];
        else              v = ((const float4*)W3)[i - 576];
        Ws4[i] = v;
    }
    if (t == 0) Us[0] = U0[0];
    for (int i = t; i < 12;  i += 256) Us[1  + i] = U1[i];
    for (int i = t; i < 81;  i += 256) Us[13 + i] = U2[i];
    for (int i = t; i < 432; i += 256) Us[94 + i] = U3[i];
    __syncthreads();

    const int w = t >> 5, lane = t & 31;
    const int esub = lane >> 3, kq = lane & 7;
    const int ebase = (blockIdx.x * 8 + w) * 4;
    const int e = ebase + esub;

    // radial basis via sin recurrence (fast sincos)
    const float rv = __ldg(rr + e);
    float s, c;
    __sincosf(rv * 0.62831853071795864769f, &s, &c);
    const float scale = 0.5f * (c + 1.f) / (rv + 1e-6f);
    float rb[8];
    {
        float sp = 0.f, sc = s;
        rb[0] = sc * scale;
        #pragma unroll
        for (int i = 1; i < 8; i++) { float sn = 2.f * c * sc - sp; sp = sc; sc = sn; rb[i] = sc * scale; }
    }

    // per-lane radial float4: R4[g*(g+1)/2+lp] at channels [4kq..4kq+3] of group g
    float4 R4[10];
    #pragma unroll
    for (int g = 0; g < 4; g++) {
        const int ch4 = (3 - g) * 8 + kq;
        #pragma unroll
        for (int lp = 0; lp <= g; lp++) {
            const int wo4 = (lp == 0) ? 0 : (lp == 1) ? 256 : (lp == 2) ? 448 : 576;
            const int KL4 = 8 * (4 - lp);
            float4 a = make_float4(0.f, 0.f, 0.f, 0.f);
            #pragma unroll
            for (int i = 0; i < 8; i++) {
                float4 wv = Ws4[wo4 + i * KL4 + ch4];
                a.x = fmaf(rb[i], wv.x, a.x);
                a.y = fmaf(rb[i], wv.y, a.y);
                a.z = fmaf(rb[i], wv.z, a.z);
                a.w = fmaf(rb[i], wv.w, a.w);
            }
            R4[g * (g + 1) / 2 + lp] = a;
        }
    }

    // stage sh: 64 values per warp (4 edges x 16)
    #pragma unroll
    for (int j = 0; j < 2; j++) {
        int sidx = j * 32 + lane;
        int es2 = sidx >> 4, sl = sidx & 15;
        int e2 = ebase + es2;
        float v;
        if      (sl == 0) v = __ldg(sh0 + e2);
        else if (sl < 4)  v = __ldg(sh1 + e2 * 3 + (sl - 1));
        else if (sl < 9)  v = __ldg(sh2 + e2 * 5 + (sl - 4));
        else              v = __ldg(sh3 + e2 * 7 + (sl - 9));
        shS[w][es2][sl] = v;
    }
    __syncwarp();

    // cooperative S table: 640 slots/warp. slot = esub*160 + dd*4 + lp
    {
        float* se = (float*)&seS[w][0][0];
        #pragma unroll
        for (int i = 0; i < 20; i++) {
            int slot = i * 32 + lane;
            int es3 = slot / 160;
            int rem = slot - es3 * 160;
            int dd = rem >> 2, lp = rem & 3;
            int g = dd2g(dd);
            float v = 0.f;
            if (lp <= g) {
                int d = dd - goff_d(g);
                int ub = goff_u(g) + d * (g + 1) * (g + 1) + lp * lp;
                for (int mm = 0; mm < 2 * lp + 1; mm++)
                    v = fmaf(Us[ub + mm], shS[w][es3][lp * lp + mm], v);
            }
            se[slot] = v;
        }
    }
    __syncwarp();

    // center/neighbor per edge-sub via shuffle
    int vt = 0;
    if (lane < 4)      vt = __ldg(centers + ebase + lane);
    else if (lane < 8) vt = __ldg(neighbors + ebase + lane - 4);
    const int ctr = __shfl_sync(0xffffffffu, vt, esub);
    const int nbr = __shfl_sync(0xffffffffu, vt, 4 + esub);

    const float4* uf = (const float4*)(g_uncf + (size_t)nbr * 1280) + kq;
    float*        pl = g_pool + (size_t)ctr * 1280 + 4 * kq;

    #pragma unroll
    for (int dd = 0; dd < 40; dd++) {
        const int g  = (dd == 0) ? 0 : (dd < 4) ? 1 : (dd < 13) ? 2 : 3;
        const int cb = g * (g + 1) / 2;
        const float4 s4 = seS[w][esub][dd];
        float4 u;
        u.x = R4[cb].x * s4.x; u.y = R4[cb].y * s4.x;
        u.z = R4[cb].z * s4.x; u.w = R4[cb].w * s4.x;
        if (g >= 1) {
            u.x = fmaf(R4[cb + 1].x, s4.y, u.x); u.y = fmaf(R4[cb + 1].y, s4.y, u.y);
            u.z = fmaf(R4[cb + 1].z, s4.y, u.z); u.w = fmaf(R4[cb + 1].w, s4.y, u.w);
        }
        if (g >= 2) {
            u.x = fmaf(R4[cb + 2].x, s4.z, u.x); u.y = fmaf(R4[cb + 2].y, s4.z, u.y);
            u.z = fmaf(R4[cb + 2].z, s4.z, u.z); u.w = fmaf(R4[cb + 2].w, s4.z, u.w);
        }
        if (g >= 3) {
            u.x = fmaf(R4[cb + 3].x, s4.w, u.x); u.y = fmaf(R4[cb + 3].y, s4.w, u.y);
            u.z = fmaf(R4[cb + 3].z, s4.w, u.z); u.w = fmaf(R4[cb + 3].w, s4.w, u.w);
        }
        float4 f4 = __ldg(uf + dd * 8);
        float4 m;
        m.x = u.x * f4.x; m.y = u.y * f4.y; m.z = u.z * f4.z; m.w = u.w * f4.w;
        asm volatile("red.global.add.v4.f32 [%0], {%1, %2, %3, %4};"
                     :: "l"(pl + dd * 32), "f"(m.x), "f"(m.y), "f"(m.z), "f"(m.w)
                     : "memory");
    }
}

// ---------------------------------------------------------------------------
// K3: 16 atoms per block; all Wlin cached in dynamic smem (120 KB)
// ---------------------------------------------------------------------------
__global__ void __launch_bounds__(256) k_out(
    const float* __restrict__ f0, const float* __restrict__ f1,
    const float* __restrict__ f2, const float* __restrict__ f3,
    const float* __restrict__ U0, const float* __restrict__ U1,
    const float* __restrict__ U2, const float* __restrict__ U3,
    const float* __restrict__ Wl0, const float* __restrict__ Wl1,
    const float* __restrict__ Wl2, const float* __restrict__ Wl3,
    float* __restrict__ out)
{
    extern __shared__ float Wsh[];   // 30720 floats = Wl0(16384) Wl1(9216) Wl2(4096) Wl3(1024)
    __shared__ float ps[1280];
    __shared__ float xs[960];
    __shared__ float Us[526];
    const int t = threadIdx.x;

    for (int i = t; i < 7680; i += 256) {
        float4 v;
        if      (i < 4096) v = ((const float4*)Wl0)[i];
        else if (i < 6400) v = ((const float4*)Wl1)[i - 4096];
        else if (i < 7424) v = ((const float4*)Wl2)[i - 6400];
        else               v = ((const float4*)Wl3)[i - 7424];
        ((float4*)Wsh)[i] = v;
    }
    if (t == 0) Us[0] = U0[0];
    for (int i = t; i < 12;  i += 256) Us[1  + i] = U1[i];
    for (int i = t; i < 81;  i += 256) Us[13 + i] = U2[i];
    for (int i = t; i < 432; i += 256) Us[94 + i] = U3[i];
    __syncthreads();

    const int lane = t & 31, row = t >> 5;

    for (int a = 0; a < 16; a++) {
        const int n = blockIdx.x * 16 + a;
        for (int i = t; i < 320; i += 256)
            ((float4*)ps)[i] = ((const float4*)(g_pool + (size_t)n * 1280))[i];
        __syncthreads();

        // couple: x_g[m][k] = sum_d U_g[d][m] * pool[g][d][k]
        #pragma unroll
        for (int i = 0; i < 4; i++) {
            int gm = row + 8 * i;
            if (gm < 30) {
                int g = (gm == 0) ? 0 : (gm < 5) ? 1 : (gm < 14) ? 2 : 3;
                int m = gm - ((g == 0) ? 0 : (g == 1) ? 1 : (g == 2) ? 5 : 14);
                int doff = goff_d(g);
                int gp1s = (g + 1) * (g + 1);
                int p3 = pow3g(g);
                int uo = goff_u(g) + m;
                float acc = 0.f;
                for (int d = 0; d < p3; d++)
                    acc = fmaf(Us[uo + d * gp1s], ps[(doff + d) * 32 + lane], acc);
                xs[gm * 32 + lane] = acc;
            }
        }
        __syncthreads();

        if (t < 240) {
            int l, m, q4, K, woff4; const float* F; size_t obase;
            if (t < 32)       { l = 0; K = 128; woff4 = 0;    F = f0; m = 0;            q4 = t;            obase = 0; }
            else if (t < 104) { l = 1; K = 96;  woff4 = 4096; F = f1; int u = t - 32;  m = u / 24; q4 = u % 24; obase = 1280000; }
            else if (t < 184) { l = 2; K = 64;  woff4 = 6400; F = f2; int u = t - 104; m = u / 16; q4 = u % 16; obase = 4160000; }
            else              { l = 3; K = 32;  woff4 = 7424; F = f3; int u = t - 184; m = u / 8;  q4 = u % 8;  obase = 7360000; }
            const int rows = 2 * l + 1;
            const int Kq = K >> 2;
            float4 a4 = make_float4(0.f, 0.f, 0.f, 0.f);
            const int mrow = l * l + m;
            for (int j = 0; j < 4 - l; j++) {
                int g = l + j;
                int gm = ((g == 0) ? 0 : (g == 1) ? 1 : (g == 2) ? 5 : 14) + mrow;
                const float4* Wr = (const float4*)Wsh + woff4 + (size_t)(32 * j) * Kq + q4;
                #pragma unroll
                for (int k = 0; k < 32; k++) {
                    float xv = xs[gm * 32 + k];
                    float4 wv = Wr[(size_t)k * Kq];
                    a4.x = fmaf(xv, wv.x, a4.x);
                    a4.y = fmaf(xv, wv.y, a4.y);
                    a4.z = fmaf(xv, wv.z, a4.z);
                    a4.w = fmaf(xv, wv.w, a4.w);
                }
            }
            size_t rel4 = ((size_t)n * rows + m) * Kq + q4;
            float4 fv = __ldg((const float4*)F + rel4);
            float4 ov = make_float4(fv.x + a4.x, fv.y + a4.y, fv.z + a4.z, fv.w + a4.w);
            ((float4*)out)[obase / 4 + rel4] = ov;
        }
        __syncthreads();
    }
}

// ---------------------------------------------------------------------------
extern "C" void kernel_launch(void* const* d_in, const int* in_sizes, int n_in,
                              void* d_out, int out_size)
{
    (void)n_in; (void)out_size;
    const float *Rr, *SH[4], *FT[4], *WR[4], *UU[4], *WL[4];
    const int *CT, *NB;
    if (in_sizes[2] == 1280000) {
        Rr = (const float*)d_in[0];
        for (int l = 0; l < 4; l++) {
            SH[l] = (const float*)d_in[1 + 5 * l];
            FT[l] = (const float*)d_in[2 + 5 * l];
            WR[l] = (const float*)d_in[3 + 5 * l];
            UU[l] = (const float*)d_in[4 + 5 * l];
            WL[l] = (const float*)d_in[5 + 5 * l];
        }
        CT = (const int*)d_in[21]; NB = (const int*)d_in[22];
    } else {
        Rr = (const float*)d_in[0];
        for (int l = 0; l < 4; l++) {
            SH[l] = (const float*)d_in[1 + l];
            FT[l] = (const float*)d_in[5 + l];
            WR[l] = (const float*)d_in[9 + l];
            UU[l] = (const float*)d_in[13 + l];
            WL[l] = (const float*)d_in[17 + l];
        }
        CT = (const int*)d_in[21]; NB = (const int*)d_in[22];
    }

    static bool attr_done = false;
    if (!attr_done) {
        cudaFuncSetAttribute(k_out, cudaFuncAttributeMaxDynamicSharedMemorySize, 30720 * 4);
        attr_done = true;
    }

    void* pptr = nullptr;
    cudaGetSymbolAddress(&pptr, g_pool);
    cudaMemsetAsync(pptr, 0, sizeof(float) * (size_t)NA * 1280, 0);

    k_uncf<<<NA, 256>>>(FT[0], FT[1], FT[2], FT[3], UU[0], UU[1], UU[2], UU[3]);
    k_edge<<<NE / 32, 256>>>(Rr, SH[0], SH[1], SH[2], SH[3],
                             WR[0], WR[1], WR[2], WR[3],
                             UU[0], UU[1], UU[2], UU[3], CT, NB);
    k_out<<<NA / 16, 256, 30720 * 4>>>(FT[0], FT[1], FT[2], FT[3],
                                       UU[0], UU[1], UU[2], UU[3],
                                       WL[0], WL[1], WL[2], WL[3], (float*)d_out);
}